// round 14
// baseline (speedup 1.0000x reference)
#include <cuda_runtime.h>

#define EPSF 1e-20f

constexpr int B = 8, C = 32, O = 32, H = 256, W = 256;
constexpr int HW = H * W;                         // 65536
constexpr long long NTOT = (long long)B * O * HW;

// Scratch (allocation-free rule: __device__ globals). 128 MiB.
__device__ float2 g_pq[B * C * HW];

// Produced by K12's sentinel weight block, consumed by K3.
__device__ unsigned long long g_cwT2[C * O];     // softplus(channel_weight) transposed [c][o], pair-packed
__device__ float g_scaleCG;                      // 1/(sum_sw * sum_cw)

__device__ __forceinline__ float softplusf(float x) { return __logf(1.0f + __expf(x)); }

__device__ __forceinline__ unsigned long long pack2(float lo, float hi) {
    unsigned long long v;
    asm("mov.b64 %0, {%1, %2};" : "=l"(v) : "f"(lo), "f"(hi));
    return v;
}
__device__ __forceinline__ void unpack2(unsigned long long v, float& lo, float& hi) {
    asm("mov.b64 {%0, %1}, %2;" : "=f"(lo), "=f"(hi) : "l"(v));
}
__device__ __forceinline__ void fma2(unsigned long long& acc, unsigned long long a, unsigned long long w) {
    asm("fma.rn.f32x2 %0, %1, %2, %0;" : "+l"(acc) : "l"(a), "l"(w));
}

// ---------------------------------------------------------------------------
// K12: simplified prop (p = alpha*cgx*gx, q = alpha*cgx + beta*cd^2*interior)
// + depthwise 5x5 conv. Stores RAW (nom, denom) — the 1/sum_sw factor cancels
// in K3's ratio and is folded into g_scaleCG for the cgx output.
// Per-block weights: softplus of own 25 sw + wp (no reductions, no k0 dep).
// Sentinel block (blockIdx.x == 32, c == 0, b == 0) prepares K3's weights.
// ---------------------------------------------------------------------------
constexpr int TW = 64, TH = 32;           // tile width/height
constexpr int HST = 70;                   // halo row stride in u64 (even -> 16B aligned)

__global__ __launch_bounds__(256) void k12_prop_dwconv(
    const float* __restrict__ cd, const float* __restrict__ gx,
    const float* __restrict__ cgx, const float* __restrict__ wprop,
    const float* __restrict__ sw_raw, const float* __restrict__ cw_raw) {

    __shared__ unsigned long long sPQ[36 * HST];   // 36 x 68 halo (+pad)
    __shared__ unsigned long long sw2[25];
    __shared__ float red[32];

    const int tid = threadIdx.x;
    const int b = blockIdx.z, c = blockIdx.y;

    // ---- Sentinel weight block: prepare K3's weights inside K12's shadow ----
    if (blockIdx.x == 32) {
        if (c != 0 || b != 0) return;
        // packed transposed channel weights + sum_cw
        float s2 = 0.f;
        for (int i = tid; i < O * C; i += 256) {
            int cc = i >> 5, o = i & 31;           // i = cc*32 + o
            float w = softplusf(cw_raw[o * C + cc]);
            g_cwT2[i] = pack2(w, w);
            s2 += w;
        }
        // sum_sw
        float s1 = 0.f;
        for (int i = tid; i < C * 25; i += 256) s1 += softplusf(sw_raw[i]);
#pragma unroll
        for (int o = 16; o; o >>= 1) {
            s1 += __shfl_down_sync(~0u, s1, o);
            s2 += __shfl_down_sync(~0u, s2, o);
        }
        if ((tid & 31) == 0) { red[tid >> 5] = s1; red[8 + (tid >> 5)] = s2; }
        __syncthreads();
        if (tid == 0) {
            float a = 0.f, bb = 0.f;
            for (int i = 0; i < 8; i++) { a += red[i]; bb += red[8 + i]; }
            g_scaleCG = 1.0f / (a * bb);
        }
        return;
    }

    const int h0 = (blockIdx.x >> 2) * TH;         // 8 row-tiles
    const int w0 = (blockIdx.x & 3) * TW;          // 4 col-tiles

    // per-block weights: own 25 softplus (no inv), redundant alpha/beta
    if (tid < 25) {
        float w = softplusf(sw_raw[c * 25 + tid]);
        sw2[tid] = pack2(w, w);
    }
    const float wp = softplusf(wprop[c]);
    const float beta = __fdividef(1.0f, 1.0f + wp);
    const float alpha = wp * beta;

    const size_t plane = ((size_t)b * C + c) * HW;

    // Phase A: 36 rows x 34 aligned pixel-pairs = 1224 jobs
    for (int idx = tid; idx < 36 * 34; idx += 256) {
        int hh = idx / 34, pw = idx - hh * 34;
        int gh = h0 + hh - 2, gw = w0 + pw * 2 - 2;   // gw even; pair fully in or out
        unsigned long long v0 = 0ULL, v1 = 0ULL;
        if ((unsigned)gh < (unsigned)H && (unsigned)gw < (unsigned)W) {
            size_t g = plane + (size_t)gh * W + gw;
            float2 cd2 = *(const float2*)(cd + g);
            float2 gx2 = *(const float2*)(gx + g);
            float2 cg2 = *(const float2*)(cgx + g);
            float m0 = alpha * cg2.x, m1 = alpha * cg2.y;
            float cz0 = (gw == 0)         ? 0.f : cd2.x;   // left edge col
            float cz1 = (gw + 1 == W - 1) ? 0.f : cd2.y;   // right edge col
            v0 = pack2(m0 * gx2.x, fmaf(beta * cz0, cz0, m0));
            v1 = pack2(m1 * gx2.y, fmaf(beta * cz1, cz1, m1));
        }
        *(ulonglong2*)(sPQ + hh * HST + pw * 2) = make_ulonglong2(v0, v1);
    }
    __syncthreads();

    // Phase B: thread (tx, ty) -> cols 2tx..2tx+1, rows ty*4..ty*4+3
    const int tx = tid & 31, ty = tid >> 5;
    const int r0 = ty * 4;
    const int c0 = 2 * tx;
    unsigned long long acc0[4] = {0ULL, 0ULL, 0ULL, 0ULL};  // left col
    unsigned long long acc1[4] = {0ULL, 0ULL, 0ULL, 0ULL};  // right col

#pragma unroll
    for (int i = 0; i < 8; i++) {                  // halo rows r0 .. r0+7
        unsigned long long x[6];
        const unsigned long long* rp = sPQ + (r0 + i) * HST + c0;
        *(ulonglong2*)(x + 0) = *(const ulonglong2*)(rp + 0);
        *(ulonglong2*)(x + 2) = *(const ulonglong2*)(rp + 2);
        *(ulonglong2*)(x + 4) = *(const ulonglong2*)(rp + 4);
#pragma unroll
        for (int k = 0; k < 4; k++) {
            const int wr = i - k;
            if (wr >= 0 && wr < 5) {
#pragma unroll
                for (int j = 0; j < 5; j++) {
                    unsigned long long w = sw2[wr * 5 + j];
                    fma2(acc0[k], x[j], w);
                    fma2(acc1[k], x[j + 1], w);
                }
            }
        }
    }

    // store raw (nom, denom) pairs, 16B per thread-row
#pragma unroll
    for (int k = 0; k < 4; k++) {
        float2* dst = &g_pq[plane + (size_t)(h0 + r0 + k) * W + (w0 + c0)];
        *(float4*)dst = make_float4(((float2*)&acc0[k])->x, ((float2*)&acc0[k])->y,
                                    ((float2*)&acc1[k])->x, ((float2*)&acc1[k])->y);
    }
}

// ---------------------------------------------------------------------------
// K3: 1x1 channel conv (32 -> 32). Block = 128 contiguous pixels of one batch.
// Warp-per-pixel-group, lane = output channel.
// ---------------------------------------------------------------------------
constexpr int K3_PIX = 128;
constexpr int K3_THREADS = 256;
constexpr int PQ_STRIDE = 34;                    // u64; even -> 16B aligned rows
constexpr int STG_STRIDE = 129;                  // floats; odd -> conflict-free lane writes

__global__ __launch_bounds__(K3_THREADS) void k3_chconv(const float* __restrict__ bias,
                                                        float* __restrict__ out) {
    __shared__ unsigned long long sPQ[K3_PIX * PQ_STRIDE];
    __shared__ float stage[2 * O * STG_STRIDE];

    const int tid = threadIdx.x;
    const int lane = tid & 31;
    const int warp = tid >> 5;
    const int b = blockIdx.y;
    const int pix0 = blockIdx.x * K3_PIX;

    // load pq tile: [c][px] gmem -> [px][c] smem
    const size_t base = (size_t)b * C * HW + pix0;
#pragma unroll
    for (int it = 0; it < (K3_PIX * C) / K3_THREADS; it++) {
        int idx = it * K3_THREADS + tid;
        int c = idx >> 7;
        int px = idx & (K3_PIX - 1);
        float2 pq = g_pq[base + (size_t)c * HW + px];
        sPQ[px * PQ_STRIDE + c] = pack2(pq.x, pq.y);
    }

    unsigned long long wr[C];
#pragma unroll
    for (int cc = 0; cc < C; cc++) wr[cc] = g_cwT2[cc * O + lane];
    const float bs = bias[lane];
    const float sccg = g_scaleCG;

    __syncthreads();

#pragma unroll
    for (int i = 0; i < K3_PIX / 8; i++) {
        const int px = warp * (K3_PIX / 8) + i;
        const unsigned long long* p = sPQ + px * PQ_STRIDE;
        unsigned long long a0 = 0ULL, a1 = 0ULL, a2 = 0ULL, a3 = 0ULL;
#pragma unroll
        for (int cc = 0; cc < C; cc += 4) {
            ulonglong2 x01 = *(const ulonglong2*)(p + cc);
            ulonglong2 x23 = *(const ulonglong2*)(p + cc + 2);
            fma2(a0, x01.x, wr[cc]);
            fma2(a1, x01.y, wr[cc + 1]);
            fma2(a2, x23.x, wr[cc + 2]);
            fma2(a3, x23.y, wr[cc + 3]);
        }
        float n0, d0, n1, d1, n2, d2, n3, d3;
        unpack2(a0, n0, d0); unpack2(a1, n1, d1);
        unpack2(a2, n2, d2); unpack2(a3, n3, d3);
        float n = (n0 + n1) + (n2 + n3);
        float dn = (d0 + d1) + (d2 + d3);
        stage[lane * STG_STRIDE + px]                  = __fdividef(n, dn + EPSF) + bs; // gx_out
        stage[O * STG_STRIDE + lane * STG_STRIDE + px] = dn * sccg;                     // cgx_out
    }
    __syncthreads();

    const size_t outb = (size_t)b * O * HW + pix0;
#pragma unroll
    for (int it = 0; it < (O * K3_PIX) / K3_THREADS; it++) {
        int idx = it * K3_THREADS + tid;
        int o = idx >> 7;
        int px = idx & (K3_PIX - 1);
        size_t g = outb + (size_t)o * HW + px;
        out[g]        = stage[o * STG_STRIDE + px];
        out[NTOT + g] = stage[O * STG_STRIDE + o * STG_STRIDE + px];
    }
}

// ---------------------------------------------------------------------------
extern "C" void kernel_launch(void* const* d_in, const int* in_sizes, int n_in,
                              void* d_out, int out_size) {
    const float* cd    = (const float*)d_in[1];
    const float* gx    = (const float*)d_in[2];
    const float* cgx   = (const float*)d_in[3];
    const float* wprop = (const float*)d_in[4];
    const float* sw    = (const float*)d_in[5];
    const float* cw    = (const float*)d_in[6];
    const float* bias  = (const float*)d_in[7];
    float* out = (float*)d_out;

    dim3 g12(33, C, B);            // 4x8 tiles of 64x32 per (c,b) + sentinel weight block
    k12_prop_dwconv<<<g12, 256>>>(cd, gx, cgx, wprop, sw, cw);

    dim3 g3(HW / K3_PIX, B);       // 512 pixel-chunks per batch
    k3_chconv<<<g3, K3_THREADS>>>(bias, out);
}

// round 15
// speedup vs baseline: 1.2007x; 1.2007x over previous
#include <cuda_runtime.h>

#define EPSF 1e-20f

constexpr int B = 8, C = 32, O = 32, H = 256, W = 256;
constexpr int HW = H * W;                         // 65536
constexpr long long NTOT = (long long)B * O * HW;

// Scratch (allocation-free rule: __device__ globals). 128 MiB total.
__device__ float g_p[B * C * HW];                 // conv nominator (raw)
__device__ float g_q[B * C * HW];                 // conv denominator (raw)

// k0 outputs
__device__ unsigned long long g_cwT2[C * O];      // softplus(channel_weight) transposed [c][o], pair-packed
__device__ float g_scaleCG;                       // 1/(sum_sw * sum_cw)

__device__ __forceinline__ float softplusf(float x) { return __logf(1.0f + __expf(x)); }

__device__ __forceinline__ unsigned long long pack2(float lo, float hi) {
    unsigned long long v;
    asm("mov.b64 %0, {%1, %2};" : "=l"(v) : "f"(lo), "f"(hi));
    return v;
}
__device__ __forceinline__ void unpack2(unsigned long long v, float& lo, float& hi) {
    asm("mov.b64 {%0, %1}, %2;" : "=f"(lo), "=f"(hi) : "l"(v));
}
__device__ __forceinline__ void fma2(unsigned long long& acc, unsigned long long a, unsigned long long w) {
    asm("fma.rn.f32x2 %0, %1, %2, %0;" : "+l"(acc) : "l"(a), "l"(w));
}

// ---------------------------------------------------------------------------
// K0: packed transposed channel weights + 1/(sum_sw*sum_cw).
// ---------------------------------------------------------------------------
__global__ void k0_weights(const float* __restrict__ sw_raw,
                           const float* __restrict__ cw_raw) {
    __shared__ float red[64];
    const int t = threadIdx.x;            // 1024 threads

    float s1 = 0.f;
    for (int i = t; i < C * 25; i += 1024) s1 += softplusf(sw_raw[i]);

    float s2 = 0.f;
    for (int i = t; i < O * C; i += 1024) {
        int c = i >> 5, o = i & 31;       // i = c*32 + o
        float w = softplusf(cw_raw[o * C + c]);
        g_cwT2[i] = pack2(w, w);
        s2 += w;
    }
#pragma unroll
    for (int o = 16; o; o >>= 1) {
        s1 += __shfl_down_sync(~0u, s1, o);
        s2 += __shfl_down_sync(~0u, s2, o);
    }
    if ((t & 31) == 0) { red[t >> 5] = s1; red[32 + (t >> 5)] = s2; }
    __syncthreads();
    if (t == 0) {
        float a = 0.f, b = 0.f;
        for (int i = 0; i < 32; i++) { a += red[i]; b += red[32 + i]; }
        g_scaleCG = 1.0f / (a * b);
    }
}

// ---------------------------------------------------------------------------
// K12: simplified prop (p = alpha*cgx*gx, q = alpha*cgx + beta*cd^2*interior)
// + depthwise 5x5 conv (raw weights; 1/sum_sw cancels in K3's ratio and is
// folded into g_scaleCG). One block = one (b, c, 64x32 tile).
// Outputs de-interleaved into g_p / g_q planes.
// ---------------------------------------------------------------------------
constexpr int TW = 64, TH = 32;           // tile width/height
constexpr int HST = 70;                   // halo row stride in u64 (even -> 16B aligned)

__global__ __launch_bounds__(256) void k12_prop_dwconv(
    const float* __restrict__ cd, const float* __restrict__ gx,
    const float* __restrict__ cgx, const float* __restrict__ wprop,
    const float* __restrict__ sw_raw) {

    __shared__ unsigned long long sPQ[36 * HST];   // 36 x 68 halo (+pad)
    __shared__ unsigned long long sw2[25];

    const int tid = threadIdx.x;
    const int b = blockIdx.z, c = blockIdx.y;
    const int h0 = (blockIdx.x >> 2) * TH;         // 8 row-tiles
    const int w0 = (blockIdx.x & 3) * TW;          // 4 col-tiles

    if (tid < 25) {
        float w = softplusf(sw_raw[c * 25 + tid]);
        sw2[tid] = pack2(w, w);
    }
    const float wp = softplusf(wprop[c]);
    const float beta = __fdividef(1.0f, 1.0f + wp);
    const float alpha = wp * beta;

    const size_t plane = ((size_t)b * C + c) * HW;

    // Phase A: 36 rows x 34 aligned pixel-pairs = 1224 jobs
    for (int idx = tid; idx < 36 * 34; idx += 256) {
        int hh = idx / 34, pw = idx - hh * 34;
        int gh = h0 + hh - 2, gw = w0 + pw * 2 - 2;   // gw even; pair fully in or out
        unsigned long long v0 = 0ULL, v1 = 0ULL;
        if ((unsigned)gh < (unsigned)H && (unsigned)gw < (unsigned)W) {
            size_t g = plane + (size_t)gh * W + gw;
            float2 cd2 = *(const float2*)(cd + g);
            float2 gx2 = *(const float2*)(gx + g);
            float2 cg2 = *(const float2*)(cgx + g);
            float m0 = alpha * cg2.x, m1 = alpha * cg2.y;
            float cz0 = (gw == 0)         ? 0.f : cd2.x;   // left edge col
            float cz1 = (gw + 1 == W - 1) ? 0.f : cd2.y;   // right edge col
            v0 = pack2(m0 * gx2.x, fmaf(beta * cz0, cz0, m0));
            v1 = pack2(m1 * gx2.y, fmaf(beta * cz1, cz1, m1));
        }
        *(ulonglong2*)(sPQ + hh * HST + pw * 2) = make_ulonglong2(v0, v1);
    }
    __syncthreads();

    // Phase B: thread (tx, ty) -> cols 2tx..2tx+1, rows ty*4..ty*4+3
    const int tx = tid & 31, ty = tid >> 5;
    const int r0 = ty * 4;
    const int c0 = 2 * tx;
    unsigned long long acc0[4] = {0ULL, 0ULL, 0ULL, 0ULL};  // left col
    unsigned long long acc1[4] = {0ULL, 0ULL, 0ULL, 0ULL};  // right col

#pragma unroll
    for (int i = 0; i < 8; i++) {                  // halo rows r0 .. r0+7
        unsigned long long x[6];
        const unsigned long long* rp = sPQ + (r0 + i) * HST + c0;
        *(ulonglong2*)(x + 0) = *(const ulonglong2*)(rp + 0);
        *(ulonglong2*)(x + 2) = *(const ulonglong2*)(rp + 2);
        *(ulonglong2*)(x + 4) = *(const ulonglong2*)(rp + 4);
#pragma unroll
        for (int k = 0; k < 4; k++) {
            const int wr = i - k;
            if (wr >= 0 && wr < 5) {
#pragma unroll
                for (int j = 0; j < 5; j++) {
                    unsigned long long w = sw2[wr * 5 + j];
                    fma2(acc0[k], x[j], w);
                    fma2(acc1[k], x[j + 1], w);
                }
            }
        }
    }

    // de-interleaved stores: (n left, n right) -> g_p, (d left, d right) -> g_q
#pragma unroll
    for (int k = 0; k < 4; k++) {
        float nL, dL, nR, dR;
        unpack2(acc0[k], nL, dL);
        unpack2(acc1[k], nR, dR);
        size_t g = plane + (size_t)(h0 + r0 + k) * W + (w0 + c0);
        *(float2*)(g_p + g) = make_float2(nL, nR);
        *(float2*)(g_q + g) = make_float2(dL, dR);
    }
}

// ---------------------------------------------------------------------------
// K3: 1x1 channel conv (32 -> 32). Block = 128 contiguous pixels of one batch.
// p/q staged in [c][px] smem (straight copy, no transpose, min-phase STS.128).
// Compute: warp handles 16 px in groups of 4; per channel one broadcast
// LDS.128 gives 4 pixels -> 2 FMA2 against duplicated weight (lane = o).
// ---------------------------------------------------------------------------
constexpr int K3_PIX = 128;
constexpr int K3_THREADS = 256;
constexpr int ROW = 132;                          // float row stride (16B-aligned)
constexpr int STG_STRIDE = 129;                   // floats; conflict-free lane writes

__global__ __launch_bounds__(K3_THREADS) void k3_chconv(const float* __restrict__ bias,
                                                        float* __restrict__ out) {
    __shared__ float sP[C * ROW];                 // 16896 B
    __shared__ float sQ[C * ROW];                 // 16896 B
    __shared__ float stage[2 * O * STG_STRIDE];   // 33024 B

    const int tid = threadIdx.x;
    const int lane = tid & 31;
    const int warp = tid >> 5;
    const int b = blockIdx.y;
    const int pix0 = blockIdx.x * K3_PIX;

    // straight copy: 32 channels x 128 px per plane, float4 granularity
    const size_t base = (size_t)b * C * HW + pix0;
#pragma unroll
    for (int it = 0; it < 4; it++) {              // 1024 float4 per plane / 256 thr
        int idx = it * K3_THREADS + tid;
        int c = idx >> 5;                         // 32 float4 per row
        int x4 = (idx & 31) * 4;
        *(float4*)(sP + c * ROW + x4) = *(const float4*)(g_p + base + (size_t)c * HW + x4);
        *(float4*)(sQ + c * ROW + x4) = *(const float4*)(g_q + base + (size_t)c * HW + x4);
    }

    unsigned long long wr[C];
#pragma unroll
    for (int cc = 0; cc < C; cc++) wr[cc] = g_cwT2[cc * O + lane];
    const float bs = bias[lane];
    const float sccg = g_scaleCG;

    __syncthreads();

#pragma unroll
    for (int gi = 0; gi < 4; gi++) {              // 4 groups of 4 px per warp
        const int px = warp * 16 + gi * 4;
        unsigned long long an01 = 0ULL, an23 = 0ULL, ad01 = 0ULL, ad23 = 0ULL;
#pragma unroll
        for (int cc = 0; cc < C; cc++) {
            float4 p4 = *(const float4*)(sP + cc * ROW + px);  // broadcast LDS.128
            float4 q4 = *(const float4*)(sQ + cc * ROW + px);
            unsigned long long w = wr[cc];
            fma2(an01, pack2(p4.x, p4.y), w);
            fma2(an23, pack2(p4.z, p4.w), w);
            fma2(ad01, pack2(q4.x, q4.y), w);
            fma2(ad23, pack2(q4.z, q4.w), w);
        }
        float n[4], dn[4];
        unpack2(an01, n[0], n[1]);  unpack2(an23, n[2], n[3]);
        unpack2(ad01, dn[0], dn[1]); unpack2(ad23, dn[2], dn[3]);
#pragma unroll
        for (int j = 0; j < 4; j++) {
            stage[lane * STG_STRIDE + px + j]                  = __fdividef(n[j], dn[j] + EPSF) + bs;
            stage[O * STG_STRIDE + lane * STG_STRIDE + px + j] = dn[j] * sccg;
        }
    }
    __syncthreads();

    const size_t outb = (size_t)b * O * HW + pix0;
#pragma unroll
    for (int it = 0; it < (O * K3_PIX) / K3_THREADS; it++) {
        int idx = it * K3_THREADS + tid;
        int o = idx >> 7;
        int px = idx & (K3_PIX - 1);
        size_t g = outb + (size_t)o * HW + px;
        out[g]        = stage[o * STG_STRIDE + px];
        out[NTOT + g] = stage[O * STG_STRIDE + o * STG_STRIDE + px];
    }
}

// ---------------------------------------------------------------------------
extern "C" void kernel_launch(void* const* d_in, const int* in_sizes, int n_in,
                              void* d_out, int out_size) {
    const float* cd    = (const float*)d_in[1];
    const float* gx    = (const float*)d_in[2];
    const float* cgx   = (const float*)d_in[3];
    const float* wprop = (const float*)d_in[4];
    const float* sw    = (const float*)d_in[5];
    const float* cw    = (const float*)d_in[6];
    const float* bias  = (const float*)d_in[7];
    float* out = (float*)d_out;

    k0_weights<<<1, 1024>>>(sw, cw);

    dim3 g12(32, C, B);            // 4x8 tiles of 64x32, per (c, b)
    k12_prop_dwconv<<<g12, 256>>>(cd, gx, cgx, wprop, sw);

    dim3 g3(HW / K3_PIX, B);       // 512 pixel-chunks per batch
    k3_chconv<<<g3, K3_THREADS>>>(bias, out);
}